// round 1
// baseline (speedup 1.0000x reference)
#include <cuda_runtime.h>
#include <cuda_bf16.h>

// Problem constants (setup_inputs: N=8192, limit_broad=4N, limit_narrow=N).
// Device scratch is statically sized for these; logic reads actual limits
// from the device-side scalar inputs and clamps to array capacity.
#define MAXN 8192
#define MAXB (4 * MAXN)

__device__ int    g_row_cnt[MAXN];
__device__ int    g_row_off[MAXN];
__device__ int    g_total;
__device__ int    g_pair[MAXB];      // packed i*n + j, row-major ascending
__device__ int    g_hit[MAXB];
__device__ float2 g_delta[MAXB];     // 0.5 * penetration vector

// ---------------------------------------------------------------------------
// Kernel 1: per-row overlap count. One warp per row i, lanes stride j > i.
// ---------------------------------------------------------------------------
__global__ void count_rows_kernel(const float2* __restrict__ c,
                                  const float*  __restrict__ r, int n) {
    int warp = (blockIdx.x * blockDim.x + threadIdx.x) >> 5;
    int lane = threadIdx.x & 31;
    if (warp >= n) return;
    const int i = warp;
    const float2 ci = c[i];
    const float  ri = r[i];
    int cnt = 0;
    for (int j = i + 1 + lane; j < n; j += 32) {
        float2 cj = c[j];
        float rs = ri + r[j];
        if (fabsf(ci.x - cj.x) <= rs && fabsf(ci.y - cj.y) <= rs) cnt++;
    }
    #pragma unroll
    for (int o = 16; o; o >>= 1) cnt += __shfl_down_sync(0xFFFFFFFFu, cnt, o);
    if (lane == 0) g_row_cnt[i] = cnt;
}

// ---------------------------------------------------------------------------
// Kernel 2: exclusive scan of row counts (single block, 1024 thr x 8 elems).
// ---------------------------------------------------------------------------
__global__ void scan_rows_kernel(int n) {
    __shared__ int s[1024];
    const int t = threadIdx.x;
    const int base = t * 8;
    int local[8];
    int sum = 0;
    #pragma unroll
    for (int k = 0; k < 8; k++) {
        int idx = base + k;
        int v = (idx < n) ? g_row_cnt[idx] : 0;
        local[k] = sum;        // exclusive within-thread
        sum += v;
    }
    s[t] = sum;
    __syncthreads();
    // Hillis-Steele inclusive scan over per-thread sums
    for (int o = 1; o < 1024; o <<= 1) {
        int x = (t >= o) ? s[t - o] : 0;
        __syncthreads();
        s[t] += x;
        __syncthreads();
    }
    int excl = s[t] - sum;
    #pragma unroll
    for (int k = 0; k < 8; k++) {
        int idx = base + k;
        if (idx < n) g_row_off[idx] = excl + local[k];
    }
    if (t == 1023) g_total = s[1023];
}

// ---------------------------------------------------------------------------
// Kernel 3: write packed pairs at exact row-major ranks (ballot ranking).
// ---------------------------------------------------------------------------
__global__ void write_pairs_kernel(const float2* __restrict__ c,
                                   const float*  __restrict__ r, int n,
                                   const int* __restrict__ d_lb) {
    int warp = (blockIdx.x * blockDim.x + threadIdx.x) >> 5;
    int lane = threadIdx.x & 31;
    if (warp >= n) return;
    const int i = warp;
    const float2 ci = c[i];
    const float  ri = r[i];
    const int limitb = min(*d_lb, MAXB);
    int off = g_row_off[i];
    for (int j0 = i + 1; j0 < n; j0 += 32) {
        int j = j0 + lane;
        bool ov = false;
        if (j < n) {
            float2 cj = c[j];
            float rs = ri + r[j];
            ov = (fabsf(ci.x - cj.x) <= rs && fabsf(ci.y - cj.y) <= rs);
        }
        unsigned m = __ballot_sync(0xFFFFFFFFu, ov);
        if (ov) {
            int rank = off + __popc(m & ((1u << lane) - 1u));
            if (rank < limitb) g_pair[rank] = i * n + j;
        }
        off += __popc(m);
        if (off >= limitb) break;   // uniform across warp (off is uniform)
    }
}

// ---------------------------------------------------------------------------
// Kernel 4: narrow phase on candidate slots.
// ---------------------------------------------------------------------------
__global__ void narrow_kernel(const float2* __restrict__ c,
                              const float*  __restrict__ r, int n,
                              const int* __restrict__ d_lb) {
    int s = blockIdx.x * blockDim.x + threadIdx.x;
    const int limitb = min(*d_lb, MAXB);
    if (s >= limitb) return;
    const int total = min(g_total, limitb);
    int hit = 0;
    float2 delta = make_float2(0.f, 0.f);
    if (s < total) {
        int p = g_pair[s];
        int i = p / n;
        int j = p - i * n;
        float2 ci = c[i], cj = c[j];
        float dx = cj.x - ci.x;
        float dy = cj.y - ci.y;
        float dist = sqrtf(dx * dx + dy * dy + 1e-12f);
        float depth = r[i] + r[j] - dist;
        if (depth > 0.f) {
            hit = 1;
            float sc = 0.5f * depth / dist;
            delta = make_float2(sc * dx, sc * dy);
        }
    }
    g_hit[s] = hit;
    g_delta[s] = delta;
}

// ---------------------------------------------------------------------------
// Kernel 5: single-block scan of hit flags + ordered scatter of first
// limit_narrow hits.
// ---------------------------------------------------------------------------
__global__ void resolve_kernel(float* __restrict__ out, int n,
                               const int* __restrict__ d_lb,
                               const int* __restrict__ d_ln) {
    __shared__ int s[1024];
    const int t = threadIdx.x;
    const int limitb = min(*d_lb, MAXB);
    const int ln = *d_ln;
    const int items = (limitb + 1023) / 1024;
    const int start = t * items;
    const int end = min(start + items, limitb);

    int sum = 0;
    for (int k = start; k < end; k++) sum += g_hit[k];
    s[t] = sum;
    __syncthreads();
    for (int o = 1; o < 1024; o <<= 1) {
        int x = (t >= o) ? s[t - o] : 0;
        __syncthreads();
        s[t] += x;
        __syncthreads();
    }
    int rank = s[t] - sum;   // exclusive prefix for this thread's range
    for (int k = start; k < end; k++) {
        if (g_hit[k]) {
            if (rank < ln) {
                int p = g_pair[k];
                int i = p / n;
                int j = p - i * n;
                float2 d = g_delta[k];
                atomicAdd(&out[2 * i + 0], -d.x);
                atomicAdd(&out[2 * i + 1], -d.y);
                atomicAdd(&out[2 * j + 0],  d.x);
                atomicAdd(&out[2 * j + 1],  d.y);
            }
            rank++;
        }
    }
}

// ---------------------------------------------------------------------------
extern "C" void kernel_launch(void* const* d_in, const int* in_sizes, int n_in,
                              void* d_out, int out_size) {
    const float2* centers = (const float2*)d_in[0];
    const float*  radii   = (const float*)d_in[1];
    const int*    d_lb    = (const int*)d_in[2];
    const int*    d_ln    = (const int*)d_in[3];
    const int n = in_sizes[1];            // number of bodies
    float* out = (float*)d_out;

    // out starts as a copy of centers
    cudaMemcpyAsync(out, centers, (size_t)n * 2 * sizeof(float),
                    cudaMemcpyDeviceToDevice);

    const int warps_per_block = 8;        // 256 threads
    const int nblocks = (n + warps_per_block - 1) / warps_per_block;

    count_rows_kernel<<<nblocks, 256>>>(centers, radii, n);
    scan_rows_kernel<<<1, 1024>>>(n);
    write_pairs_kernel<<<nblocks, 256>>>(centers, radii, n, d_lb);

    const int lb_host = 4 * n;            // grid sizing only; logic uses device value
    narrow_kernel<<<(lb_host + 255) / 256, 256>>>(centers, radii, n, d_lb);
    resolve_kernel<<<1, 1024>>>(out, n, d_lb, d_ln);
}